// round 2
// baseline (speedup 1.0000x reference)
#include <cuda_runtime.h>
#include <cuda_bf16.h>
#include <math.h>

#define BATCH 8
#define SEQ   4096
#define HID   256
#define NF    6

// Scratch for combined per-batch weights M_b[h][k] = sum_f W[f][h][k] * sin(freq_f*t_b + phase[f][k])
__device__ float g_M[BATCH * HID * HID];  // 2 MB

// ---------------------------------------------------------------------------
// Kernel 1: build M_b.  grid = (HID, BATCH), 256 threads (one per k column).
// ---------------------------------------------------------------------------
__global__ __launch_bounds__(256) void build_M_kernel(
    const float* __restrict__ W,      // [F, H, H]
    const float* __restrict__ phase,  // [F, H]
    const float* __restrict__ t)      // [B, 1]
{
    const int h = blockIdx.x;
    const int b = blockIdx.y;
    const int k = threadIdx.x;
    const float tb = t[b];
    const float freqs[NF] = {1.f, 2.f, 4.f, 8.f, 7.f, 5.f};
    float acc = 0.f;
#pragma unroll
    for (int f = 0; f < NF; f++) {
        float r = sinf(freqs[f] * tb + phase[f * HID + k]);
        acc += W[((size_t)f * HID + h) * HID + k] * r;
    }
    g_M[((size_t)b * HID + h) * HID + k] = acc;
}

// ---------------------------------------------------------------------------
// Kernel 2: batched SGEMM  Y[b] = X[b] (4096x256) @ M_b (256x256)
// 128x128 CTA tile, BK=16, 8x8 per thread, 256 threads, reg-prefetch pipeline.
// ---------------------------------------------------------------------------
#define BM 128
#define BN 128
#define BK 16
#define APAD 4   // keep 16B alignment of As rows while breaking bank conflicts

__global__ __launch_bounds__(256) void gemm_kernel(
    const float* __restrict__ X,   // [B, SEQ, HID]
    float* __restrict__ Y)         // [B, SEQ, HID]
{
    __shared__ float As[BK][BM + APAD];  // transposed A tile: As[k][m]
    __shared__ float Bs[BK][BN];         // B tile: Bs[k][n]

    const int b    = blockIdx.z;
    const int row0 = blockIdx.y * BM;
    const int col0 = blockIdx.x * BN;

    const float* A  = X   + (size_t)b * SEQ * HID;
    const float* Bm = g_M + (size_t)b * HID * HID;
    float*       C  = Y   + (size_t)b * SEQ * HID;

    const int tid = threadIdx.x;
    const int tx  = tid & 15;   // 0..15 -> 8 output cols each
    const int ty  = tid >> 4;   // 0..15 -> 8 output rows each

    float acc[8][8];
#pragma unroll
    for (int i = 0; i < 8; i++)
#pragma unroll
        for (int j = 0; j < 8; j++) acc[i][j] = 0.f;

    float4 pa[2], pb[2];

    // Prefetch first K-chunk
#pragma unroll
    for (int l = 0; l < 2; l++) {
        int e  = l * 256 + tid;
        int ra = e >> 2, ca = e & 3;               // A: 128 rows x 4 float4/row
        pa[l] = *(const float4*)&A[(size_t)(row0 + ra) * HID + ca * 4];
        int rb = e >> 5, cb = e & 31;              // B: 16 rows x 32 float4/row
        pb[l] = *(const float4*)&Bm[(size_t)rb * HID + col0 + cb * 4];
    }

    for (int k0 = 0; k0 < HID; k0 += BK) {
        // Commit prefetched chunk to shared memory
#pragma unroll
        for (int l = 0; l < 2; l++) {
            int e  = l * 256 + tid;
            int ra = e >> 2, ca = e & 3;
            As[ca * 4 + 0][ra] = pa[l].x;
            As[ca * 4 + 1][ra] = pa[l].y;
            As[ca * 4 + 2][ra] = pa[l].z;
            As[ca * 4 + 3][ra] = pa[l].w;
            int rb = e >> 5, cb = e & 31;
            *(float4*)&Bs[rb][cb * 4] = pb[l];
        }
        __syncthreads();

        // Prefetch next chunk while computing on this one
        const int kn = k0 + BK;
        if (kn < HID) {
#pragma unroll
            for (int l = 0; l < 2; l++) {
                int e  = l * 256 + tid;
                int ra = e >> 2, ca = e & 3;
                pa[l] = *(const float4*)&A[(size_t)(row0 + ra) * HID + kn + ca * 4];
                int rb = e >> 5, cb = e & 31;
                pb[l] = *(const float4*)&Bm[(size_t)(kn + rb) * HID + col0 + cb * 4];
            }
        }

#pragma unroll
        for (int kk = 0; kk < BK; kk++) {
            float ra[8], rb[8];
            *(float4*)&ra[0] = *(const float4*)&As[kk][ty * 8];
            *(float4*)&ra[4] = *(const float4*)&As[kk][ty * 8 + 4];
            *(float4*)&rb[0] = *(const float4*)&Bs[kk][tx * 8];
            *(float4*)&rb[4] = *(const float4*)&Bs[kk][tx * 8 + 4];
#pragma unroll
            for (int i = 0; i < 8; i++)
#pragma unroll
                for (int j = 0; j < 8; j++)
                    acc[i][j] = fmaf(ra[i], rb[j], acc[i][j]);
        }
        __syncthreads();
    }

    // Epilogue: each thread writes its 8x8 tile with float4 stores
#pragma unroll
    for (int i = 0; i < 8; i++) {
        size_t base = (size_t)(row0 + ty * 8 + i) * HID + col0 + tx * 8;
        *(float4*)&C[base]     = *(float4*)&acc[i][0];
        *(float4*)&C[base + 4] = *(float4*)&acc[i][4];
    }
}

// ---------------------------------------------------------------------------
extern "C" void kernel_launch(void* const* d_in, const int* in_sizes, int n_in,
                              void* d_out, int out_size) {
    const float* x     = (const float*)d_in[0];  // [8, 4096, 256]
    const float* t     = (const float*)d_in[1];  // [8, 1]
    const float* osc   = (const float*)d_in[2];  // [6, 256, 256]
    const float* phase = (const float*)d_in[3];  // [6, 256]
    float* out = (float*)d_out;                  // [8, 4096, 256]

    (void)in_sizes; (void)n_in; (void)out_size;

    build_M_kernel<<<dim3(HID, BATCH), 256>>>(osc, phase, t);
    gemm_kernel<<<dim3(HID / BN, SEQ / BM, BATCH), 256>>>(x, out);
}

// round 4
// speedup vs baseline: 2.4030x; 2.4030x over previous
#include <cuda_runtime.h>
#include <cuda_fp16.h>
#include <math.h>
#include <stdint.h>

#define BATCH 8
#define SEQ   4096
#define HID   256
#define NF    6

// Precombined per-batch weights, TRANSPOSED to [b][n][h] (n = output col,
// h = reduction dim), split into fp16 hi/lo.
__device__ __half g_Bhi[BATCH * HID * HID];   // 1 MB
__device__ __half g_Blo[BATCH * HID * HID];   // 1 MB

// ===========================================================================
// Helpers
// ===========================================================================
__device__ __forceinline__ uint32_t smem_u32(const void* p) {
    uint32_t a;
    asm("{ .reg .u64 t; cvta.to.shared.u64 t, %1; cvt.u32.u64 %0, t; }" : "=r"(a) : "l"(p));
    return a;
}
__device__ __forceinline__ void cp_async16(uint32_t dst, const void* src) {
    asm volatile("cp.async.ca.shared.global [%0], [%1], 16;" :: "r"(dst), "l"(src));
}
#define CP_COMMIT() asm volatile("cp.async.commit_group;" ::: "memory")
#define CP_WAIT0()  asm volatile("cp.async.wait_group 0;" ::: "memory")

__device__ __forceinline__ void ldmx4(uint32_t a, uint32_t r[4]) {
    asm volatile("ldmatrix.sync.aligned.m8n8.x4.shared.b16 {%0,%1,%2,%3}, [%4];"
                 : "=r"(r[0]), "=r"(r[1]), "=r"(r[2]), "=r"(r[3]) : "r"(a));
}
__device__ __forceinline__ void ldmx2(uint32_t a, uint32_t r[2]) {
    asm volatile("ldmatrix.sync.aligned.m8n8.x2.shared.b16 {%0,%1}, [%2];"
                 : "=r"(r[0]), "=r"(r[1]) : "r"(a));
}
__device__ __forceinline__ void mma16816(float c[4], const uint32_t a[4], const uint32_t b[2]) {
    asm volatile(
        "mma.sync.aligned.m16n8k16.row.col.f32.f16.f16.f32 "
        "{%0,%1,%2,%3},{%4,%5,%6,%7},{%8,%9},{%0,%1,%2,%3};"
        : "+f"(c[0]), "+f"(c[1]), "+f"(c[2]), "+f"(c[3])
        : "r"(a[0]), "r"(a[1]), "r"(a[2]), "r"(a[3]), "r"(b[0]), "r"(b[1]));
}

// Swizzled byte offset for a [r][64] fp16 tile (128B rows, 16B-chunk XOR swizzle)
__device__ __forceinline__ uint32_t sw_off(int r, int k) {
    int c = k >> 3;
    return (uint32_t)((r << 7) + (((c ^ (r & 7)) << 4)) + ((k & 7) << 1));
}

// ===========================================================================
// Kernel 1: build combined weights, transposed + fp16-split.
//   M_b[h][k] = sum_f W[f][h][k] * sin(freq_f * t_b + phase[f][k])
//   g_Bhi[b][n][h] = fp16_hi(M_b[h][n]),  g_Blo = fp16 residual
// ===========================================================================
__global__ __launch_bounds__(256) void build_M_kernel(
    const float* __restrict__ W,      // [F, H, H]
    const float* __restrict__ phase,  // [F, H]
    const float* __restrict__ t)      // [B, 1]
{
    __shared__ __half s_hi[32][HID];
    __shared__ __half s_lo[32][HID];

    const int b  = blockIdx.y;
    const int h0 = blockIdx.x * 32;
    const int k  = threadIdx.x;
    const float tb = t[b];
    const float freqs[NF] = {1.f, 2.f, 4.f, 8.f, 7.f, 5.f};
    float res[NF];
#pragma unroll
    for (int f = 0; f < NF; f++) res[f] = sinf(freqs[f] * tb + phase[f * HID + k]);

    for (int hl = 0; hl < 32; hl++) {
        float acc = 0.f;
#pragma unroll
        for (int f = 0; f < NF; f++)
            acc = fmaf(W[((size_t)f * HID + h0 + hl) * HID + k], res[f], acc);
        __half hi = __float2half_rn(acc);
        s_hi[hl][k] = hi;
        s_lo[hl][k] = __float2half_rn(acc - __half2float(hi));
    }
    __syncthreads();

    const int n = k;
    __half* dhi = &g_Bhi[((size_t)b * HID + n) * HID + h0];
    __half* dlo = &g_Blo[((size_t)b * HID + n) * HID + h0];
#pragma unroll
    for (int i0 = 0; i0 < 32; i0 += 8) {
        __half th[8], tl[8];
#pragma unroll
        for (int j = 0; j < 8; j++) { th[j] = s_hi[i0 + j][n]; tl[j] = s_lo[i0 + j][n]; }
        *(uint4*)&dhi[i0] = *(uint4*)th;
        *(uint4*)&dlo[i0] = *(uint4*)tl;
    }
}

// ===========================================================================
// Kernel 2: mma.sync GEMM.  CTA: 128 rows x 128 cols, K=256 in 4 chunks of 64.
//   D = Ahi*Bhi + Ahi*Blo + Alo*Bhi  (fp16 operands, fp32 accum)
// Double-buffered smem; cp.async for B (already fp16), reg-prefetch+split for A.
// ===========================================================================
#define ST_STRIDE 65536
#define OFF_AHI   0
#define OFF_ALO   16384
#define OFF_BHI   32768
#define OFF_BLO   49152
#define SMEM_TOTAL (2 * ST_STRIDE)   // 128 KB

__global__ __launch_bounds__(256, 1) void gemm_kernel(
    const float* __restrict__ X,   // [B, SEQ, HID]
    float* __restrict__ Y)         // [B, SEQ, HID]
{
    extern __shared__ char smem[];
    const uint32_t sb = smem_u32(smem);
    const int tid  = threadIdx.x;
    const int wid  = tid >> 5;
    const int lane = tid & 31;
    const int b    = blockIdx.z;
    const int row0 = blockIdx.y * 128;
    const int col0 = blockIdx.x * 128;

    const int wm = (wid & 1) * 64;   // warp tile: 64 rows x 32 cols
    const int wn = (wid >> 1) * 32;

    const float*  A  = X + ((size_t)b * SEQ + row0) * HID;
    const __half* Bh = g_Bhi + ((size_t)b * HID + col0) * HID;
    const __half* Bl = g_Blo + ((size_t)b * HID + col0) * HID;

    float acc[4][4][4];
#pragma unroll
    for (int i = 0; i < 4; i++)
#pragma unroll
        for (int j = 0; j < 4; j++)
#pragma unroll
            for (int q = 0; q < 4; q++) acc[i][j][q] = 0.f;

    float4 pa[8];

    // ---- prologue: chunk 0
#pragma unroll
    for (int i = 0; i < 8; i++) {
        int e = i * 256 + tid, r = e >> 4, kq = e & 15;
        pa[i] = *(const float4*)&A[(size_t)r * HID + kq * 4];
    }
#pragma unroll
    for (int i = 0; i < 4; i++) {
        int e = i * 256 + tid, r = e >> 3, cc = e & 7;
        uint32_t o = (uint32_t)((r << 7) + ((cc ^ (r & 7)) << 4));
        cp_async16(sb + OFF_BHI + o, &Bh[(size_t)r * HID + cc * 8]);
        cp_async16(sb + OFF_BLO + o, &Bl[(size_t)r * HID + cc * 8]);
    }
    CP_COMMIT();
    // convert + store A chunk 0
#pragma unroll
    for (int i = 0; i < 8; i++) {
        int e = i * 256 + tid, r = e >> 4, kq = e & 15;
        float4 v = pa[i];
        __half2 h01 = __floats2half2_rn(v.x, v.y);
        __half2 h23 = __floats2half2_rn(v.z, v.w);
        __half2 q01 = __floats2half2_rn(v.x - __half2float(__low2half(h01)),
                                        v.y - __half2float(__high2half(h01)));
        __half2 q23 = __floats2half2_rn(v.z - __half2float(__low2half(h23)),
                                        v.w - __half2float(__high2half(h23)));
        uint32_t o = (uint32_t)((r << 7) + (((kq >> 1) ^ (r & 7)) << 4) + ((kq & 1) << 3));
        uint2 hv; hv.x = *(uint32_t*)&h01; hv.y = *(uint32_t*)&h23;
        uint2 lv; lv.x = *(uint32_t*)&q01; lv.y = *(uint32_t*)&q23;
        *(uint2*)(smem + OFF_AHI + o) = hv;
        *(uint2*)(smem + OFF_ALO + o) = lv;
    }
    CP_WAIT0();
    __syncthreads();

    for (int c = 0; c < 4; c++) {
        const uint32_t stoff = (uint32_t)(c & 1) * ST_STRIDE;
        const uint32_t nxoff = (uint32_t)((c + 1) & 1) * ST_STRIDE;

        if (c < 3) {
            const int k0 = (c + 1) * 64;
#pragma unroll
            for (int i = 0; i < 8; i++) {
                int e = i * 256 + tid, r = e >> 4, kq = e & 15;
                pa[i] = *(const float4*)&A[(size_t)r * HID + k0 + kq * 4];
            }
#pragma unroll
            for (int i = 0; i < 4; i++) {
                int e = i * 256 + tid, r = e >> 3, cc = e & 7;
                uint32_t o = (uint32_t)((r << 7) + ((cc ^ (r & 7)) << 4));
                cp_async16(sb + nxoff + OFF_BHI + o, &Bh[(size_t)r * HID + k0 + cc * 8]);
                cp_async16(sb + nxoff + OFF_BLO + o, &Bl[(size_t)r * HID + k0 + cc * 8]);
            }
            CP_COMMIT();
        }

        // ---- compute on current stage: 4 k16 steps
#pragma unroll
        for (int s = 0; s < 4; s++) {
            uint32_t ah[4][4], al[4][4], bh[4][2], bl[4][2];
            const int arow = wm + (lane & 15);
            const int akk  = s * 16 + ((lane >> 4) << 3);
#pragma unroll
            for (int mi = 0; mi < 4; mi++) {
                uint32_t o = sw_off(arow + mi * 16, akk);
                ldmx4(sb + stoff + OFF_AHI + o, ah[mi]);
                ldmx4(sb + stoff + OFF_ALO + o, al[mi]);
            }
            const int bkk = s * 16 + ((lane >> 3) & 1) * 8;
#pragma unroll
            for (int nj = 0; nj < 4; nj++) {
                uint32_t o = sw_off(wn + nj * 8 + (lane & 7), bkk);
                ldmx2(sb + stoff + OFF_BHI + o, bh[nj]);
                ldmx2(sb + stoff + OFF_BLO + o, bl[nj]);
            }
#pragma unroll
            for (int mi = 0; mi < 4; mi++)
#pragma unroll
                for (int nj = 0; nj < 4; nj++) {
                    mma16816(acc[mi][nj], ah[mi], bh[nj]);
                    mma16816(acc[mi][nj], ah[mi], bl[nj]);
                    mma16816(acc[mi][nj], al[mi], bh[nj]);
                }
        }

        if (c < 3) {
#pragma unroll
            for (int i = 0; i < 8; i++) {
                int e = i * 256 + tid, r = e >> 4, kq = e & 15;
                float4 v = pa[i];
                __half2 h01 = __floats2half2_rn(v.x, v.y);
                __half2 h23 = __floats2half2_rn(v.z, v.w);
                __half2 q01 = __floats2half2_rn(v.x - __half2float(__low2half(h01)),
                                                v.y - __half2float(__high2half(h01)));
                __half2 q23 = __floats2half2_rn(v.z - __half2float(__low2half(h23)),
                                                v.w - __half2float(__high2half(h23)));
                uint32_t o = (uint32_t)((r << 7) + (((kq >> 1) ^ (r & 7)) << 4) + ((kq & 1) << 3));
                uint2 hv; hv.x = *(uint32_t*)&h01; hv.y = *(uint32_t*)&h23;
                uint2 lv; lv.x = *(uint32_t*)&q01; lv.y = *(uint32_t*)&q23;
                *(uint2*)(smem + nxoff + OFF_AHI + o) = hv;
                *(uint2*)(smem + nxoff + OFF_ALO + o) = lv;
            }
            CP_WAIT0();
        }
        __syncthreads();
    }

    // ---- epilogue: direct register -> global stores (float2 per mma tile half)
    float* C = Y + ((size_t)b * SEQ + row0) * HID + col0;
#pragma unroll
    for (int mi = 0; mi < 4; mi++) {
        int r0 = wm + mi * 16 + (lane >> 2);
#pragma unroll
        for (int nj = 0; nj < 4; nj++) {
            int cc = wn + nj * 8 + (lane & 3) * 2;
            *(float2*)&C[(size_t)r0 * HID + cc]       = make_float2(acc[mi][nj][0], acc[mi][nj][1]);
            *(float2*)&C[(size_t)(r0 + 8) * HID + cc] = make_float2(acc[mi][nj][2], acc[mi][nj][3]);
        }
    }
}

// ===========================================================================
extern "C" void kernel_launch(void* const* d_in, const int* in_sizes, int n_in,
                              void* d_out, int out_size) {
    const float* x     = (const float*)d_in[0];  // [8, 4096, 256]
    const float* t     = (const float*)d_in[1];  // [8, 1]
    const float* osc   = (const float*)d_in[2];  // [6, 256, 256]
    const float* phase = (const float*)d_in[3];  // [6, 256]
    float* out = (float*)d_out;                  // [8, 4096, 256]
    (void)in_sizes; (void)n_in; (void)out_size;

    cudaFuncSetAttribute(gemm_kernel, cudaFuncAttributeMaxDynamicSharedMemorySize, SMEM_TOTAL);

    build_M_kernel<<<dim3(8, BATCH), 256>>>(osc, phase, t);
    gemm_kernel<<<dim3(2, 32, BATCH), 256, SMEM_TOTAL>>>(x, out);
}